// round 14
// baseline (speedup 1.0000x reference)
#include <cuda_runtime.h>

#define B 4
#define L 2048
#define H 8
#define D 64
#define S 40
#define NTOP 40
#define BH (B*H)

#define KS 8            // k-splits (256 keys each)
#define NU 8            // u-chunks
#define UPC 5           // u rows per chunk (NU*UPC == NTOP)

#define CCH 64          // cumsum chunks
#define CLEN (L/CCH)    // 32 rows per chunk

#define ATT_BLOCKS (KS*NU*BH)   // 2048
#define CC_BLOCKS  (CCH*BH)     // 2048

#define FULLMASK 0xffffffffu

// Scratch (no allocations allowed)
__device__ float g_M[BH * L];
__device__ int   g_top[BH * NTOP];
__device__ float g_cs[BH * CCH * D];
__device__ float g_pl[BH * NTOP * KS];
__device__ float g_pacc[BH * NTOP * KS * D];

__device__ __forceinline__ float4 f4add(float4 a, float4 b) {
    return make_float4(a.x + b.x, a.y + b.y, a.z + b.z, a.w + b.w);
}

// ---------------------------------------------------------------------------
// K1: mscore with L1-resident K passes.
// Grid 128 (= 32 bh x 4 l-groups) -> wave-1 places 1 block/SM: private L1.
// Block = 512 threads = 16 warps; warp sweeps 32 l's. TWO passes over its
// l's: pass c only gathers K rows with (ki>>10)==c, so the pass working set
// (256 KB) is ~L1-resident -> most gather bytes never reach L2 twice.
// Gather scheme unchanged from the verified version: 8 lanes per sample,
// 4 samples (groups) per step; group-uniform membership predicate; masked
// intra-group reduce. Per-l (mx,sm) partials persist across passes in smem.
// index_sample is int32 on the wire (JAX x64-disabled downcast).
// ---------------------------------------------------------------------------
__global__ void __launch_bounds__(512)
mscore_kernel(const float* __restrict__ Q,
              const float* __restrict__ K,
              const int* __restrict__ idx) {
    int bh = blockIdx.x >> 2;
    int lg = blockIdx.x & 3;
    int b = bh >> 3, h = bh & 7;
    int tid = threadIdx.x, w = tid >> 5, lane = tid & 31;
    int g = lane >> 3, j = lane & 7;
    unsigned gm = 0xffu << (g * 8);

    __shared__ float pmx[16][32];
    __shared__ float psm[16][32];

    const float* Kb = K + ((size_t)b * L * H + h) * D;

    for (int pass = 0; pass < 2; pass++) {
        for (int il = 0; il < 32; il++) {
            int l = lg * 512 + w * 32 + il;

            const float4* q4 = (const float4*)(Q + ((size_t)(b * L + l) * H + h) * D);
            float4 qa = q4[j], qb = q4[8 + j];

            const int* srow = idx + (size_t)l * S;
            int s_lo = srow[lane];
            int s_hi = (lane < 8) ? srow[lane + 32] : 0;

            float mx = -1e30f, sm = 0.f;

            #pragma unroll
            for (int bt = 0; bt < 10; bt++) {
                int s = bt * 4 + g;
                int ki = (bt < 8) ? __shfl_sync(FULLMASK, s_lo, s)
                                  : __shfl_sync(FULLMASK, s_hi, s - 32);
                if ((ki >> 10) == pass) {               // group-uniform
                    const float4* k4 = (const float4*)(Kb + (size_t)ki * H * D);
                    float4 ka = k4[j], kb = k4[8 + j];
                    float d = qa.x*ka.x + qa.y*ka.y + qa.z*ka.z + qa.w*ka.w
                            + qb.x*kb.x + qb.y*kb.y + qb.z*kb.z + qb.w*kb.w;
                    d += __shfl_down_sync(gm, d, 4);
                    d += __shfl_down_sync(gm, d, 2);
                    d += __shfl_down_sync(gm, d, 1);
                    if (j == 0) { mx = fmaxf(mx, d); sm += d; }
                }
            }

            // combine 4 group leaders (convergent)
            if (j != 0) { mx = -1e30f; sm = 0.f; }
            mx = fmaxf(mx, __shfl_xor_sync(FULLMASK, mx, 8));
            sm +=          __shfl_xor_sync(FULLMASK, sm, 8);
            mx = fmaxf(mx, __shfl_xor_sync(FULLMASK, mx, 16));
            sm +=          __shfl_xor_sync(FULLMASK, sm, 16);

            if (lane == 0) {
                if (pass == 0) {
                    pmx[w][il] = mx; psm[w][il] = sm;
                } else {
                    float m2 = fmaxf(pmx[w][il], mx);
                    g_M[bh * L + l] = m2 - (psm[w][il] + sm) * (1.0f / (float)L);
                }
            }
        }
    }
}

// ---------------------------------------------------------------------------
// K2: topk ∪ cumsumA (independent roles; block-uniform branch).
// topk (blocks [0,BH)): top-40 of M, emitted ASCENDING (order-invariant).
// cumsumA (blocks [BH, BH+CCH*BH/2)): per-chunk V sums, 2 chunks per block.
// ---------------------------------------------------------------------------
__global__ void __launch_bounds__(256)
k2_topk_cumsumA(const float* __restrict__ V) {
    int tid = threadIdx.x;

    if (blockIdx.x < BH) {
        // ------------------- topk -------------------
        __shared__ float vals[L];
        __shared__ float wv[8];
        __shared__ int   wi[8];
        __shared__ int   sel[NTOP];
        int bh = blockIdx.x;

        for (int i = tid; i < L; i += 256) vals[i] = g_M[bh * L + i];
        __syncthreads();

        for (int t = 0; t < NTOP; t++) {
            float bv = -1e38f; int bi = 0;
            for (int i = tid; i < L; i += 256) {
                float v = vals[i];
                if (v > bv) { bv = v; bi = i; }
            }
            #pragma unroll
            for (int off = 16; off; off >>= 1) {
                float ov = __shfl_down_sync(FULLMASK, bv, off);
                int   oi = __shfl_down_sync(FULLMASK, bi, off);
                if (ov > bv || (ov == bv && oi < bi)) { bv = ov; bi = oi; }
            }
            if ((tid & 31) == 0) { wv[tid >> 5] = bv; wi[tid >> 5] = bi; }
            __syncthreads();
            if (tid == 0) {
                float fv = wv[0]; int fi = wi[0];
                #pragma unroll
                for (int ww = 1; ww < 8; ww++)
                    if (wv[ww] > fv || (wv[ww] == fv && wi[ww] < fi)) { fv = wv[ww]; fi = wi[ww]; }
                sel[t] = fi;
                vals[fi] = -1e38f;
            }
            __syncthreads();
        }

        if (tid < NTOP) {
            int mine = sel[tid], r = 0;
            #pragma unroll
            for (int i = 0; i < NTOP; i++) r += (sel[i] < mine);
            g_top[bh * NTOP + r] = mine;
        }
    } else {
        // ------------------- cumsumA -------------------
        __shared__ float4 sa[2][8][16];
        int cb = blockIdx.x - BH;
        int half = tid >> 7;
        int t = tid & 127;
        int cc2 = cb * 2 + half;
        int c = cc2 & (CCH - 1), bh = cc2 >> 6;
        int b = bh >> 3, h = bh & 7;
        int rg = t >> 4, f4 = t & 15;
        const int RS = H * D / 4;

        const float4* vb = (const float4*)(V + ((size_t)(b * L + c * CLEN + rg * 4) * H + h) * D) + f4;
        float4 s = vb[0];
        #pragma unroll
        for (int i = 1; i < 4; i++) s = f4add(s, vb[(size_t)i * RS]);

        sa[half][rg][f4] = s;
        __syncthreads();
        if (rg == 0) {
            float4 tt = sa[half][0][f4];
            #pragma unroll
            for (int i = 1; i < 8; i++) tt = f4add(tt, sa[half][i][f4]);
            ((float4*)g_cs)[(bh * CCH + c) * 16 + f4] = tt;
        }
    }
}

// ---------------------------------------------------------------------------
// K3: attn_part ∪ cumsumC (deps: topk and cumsumA, both in K2).
// Shared-memory OVERLAID via union: only one role runs per block, so attn's
// 41.6KB and cumsumC's 8KB occupy the same bytes (static smem = max, not sum).
// attn_part (blocks [0, ATT_BLOCKS)): unnormalized-exp partials (|s|<~6 so
//   exp can't overflow; Σp·v/Σp identical to softmax). Causal early exit.
// cumsumC (blocks [ATT_BLOCKS, +CC_BLOCKS)): scan, 16 subgroups x 2 rows.
// ---------------------------------------------------------------------------
struct AttnSmem {
    float s_l[UPC][32];
    float s_acc[UPC][32][64];
};
struct ScanSmem {
    float4 sp[16][16];
    float4 sg[16][16];
};
union K3Smem {
    AttnSmem a;
    ScanSmem s;
};

__global__ void __launch_bounds__(256)
k3_attn_cumsumC(const float* __restrict__ Q,
                const float* __restrict__ K,
                const float* __restrict__ V,
                float* __restrict__ out) {
    __shared__ K3Smem smu;
    int tid = threadIdx.x;

    if (blockIdx.x < ATT_BLOCKS) {
        // ------------------- attn_part -------------------
        float (*s_l)[32]      = smu.a.s_l;
        float (*s_acc)[32][64] = smu.a.s_acc;

        int ks = blockIdx.x & 7, uc = (blockIdx.x >> 3) & 7, bh = blockIdx.x >> 6;
        int b = bh >> 3, h = bh & 7;
        int u0 = uc * UPC;

        int lu[UPC];
        #pragma unroll
        for (int iu = 0; iu < UPC; iu++) lu[iu] = g_top[bh * NTOP + u0 + iu];
        int lu_hi = lu[UPC - 1];
        if (ks * 256 > lu_hi) return;      // causal early exit

        int w = tid >> 5, lane = tid & 31;
        int g = lane >> 3, j = lane & 7;

        float4 qa[UPC], qb[UPC];
        #pragma unroll
        for (int iu = 0; iu < UPC; iu++) {
            const float4* q4 = (const float4*)(Q + ((size_t)(b * L + lu[iu]) * H + h) * D);
            qa[iu] = q4[j]; qb[iu] = q4[8 + j];
        }

        float lsum[UPC];
        float4 aa[UPC], ab[UPC];
        #pragma unroll
        for (int iu = 0; iu < UPC; iu++) {
            lsum[iu] = 0.f;
            aa[iu] = make_float4(0.f, 0.f, 0.f, 0.f);
            ab[iu] = make_float4(0.f, 0.f, 0.f, 0.f);
        }

        int base = ks * 256 + w * 32;
        int nst = 0;
        if (base <= lu_hi) {
            int span = lu_hi + 1 - base;
            if (span > 32) span = 32;
            nst = (span + 3) >> 2;
        }

        const float* Kb = K + ((size_t)b * L * H + h) * D;
        const float* Vb = V + ((size_t)b * L * H + h) * D;

        for (int st = 0; st < nst; st++) {
            int t = base + st * 4 + g;
            const float4* k4 = (const float4*)(Kb + (size_t)t * H * D);
            const float4* v4 = (const float4*)(Vb + (size_t)t * H * D);
            float4 ka = k4[j], kb = k4[8 + j];
            float4 va = v4[j], vb = v4[8 + j];

            #pragma unroll
            for (int iu = 0; iu < UPC; iu++) {
                float d = qa[iu].x*ka.x + qa[iu].y*ka.y + qa[iu].z*ka.z + qa[iu].w*ka.w
                        + qb[iu].x*kb.x + qb[iu].y*kb.y + qb[iu].z*kb.z + qb[iu].w*kb.w;
                d += __shfl_xor_sync(FULLMASK, d, 4);
                d += __shfl_xor_sync(FULLMASK, d, 2);
                d += __shfl_xor_sync(FULLMASK, d, 1);
                float s = (t <= lu[iu]) ? d * 0.125f : -3e38f;
                float p = __expf(s);
                lsum[iu] += p;
                aa[iu].x += p * va.x; aa[iu].y += p * va.y;
                aa[iu].z += p * va.z; aa[iu].w += p * va.w;
                ab[iu].x += p * vb.x; ab[iu].y += p * vb.y;
                ab[iu].z += p * vb.z; ab[iu].w += p * vb.w;
            }
        }

        int gs = w * 4 + g;
        #pragma unroll
        for (int iu = 0; iu < UPC; iu++) {
            if (j == 0) s_l[iu][gs] = lsum[iu];
            *(float4*)&s_acc[iu][gs][4 * j]      = aa[iu];
            *(float4*)&s_acc[iu][gs][32 + 4 * j] = ab[iu];
        }
        __syncthreads();

        for (int i = tid; i < UPC * 64; i += 256) {
            int iu = i >> 6, d = i & 63;
            float a = 0.f;
            #pragma unroll
            for (int gsi = 0; gsi < 32; gsi++) a += s_acc[iu][gsi][d];
            g_pacc[((size_t)(bh * NTOP + u0 + iu) * KS + ks) * D + d] = a;
        }
        if (tid < UPC) {
            float lt = 0.f;
            #pragma unroll
            for (int gsi = 0; gsi < 32; gsi++) lt += s_l[tid][gsi];
            g_pl[(size_t)(bh * NTOP + u0 + tid) * KS + ks] = lt;
        }
    } else {
        // ------------------- cumsumC -------------------
        float4 (*sp)[16] = smu.s.sp;
        float4 (*sg)[16] = smu.s.sg;

        int cb = blockIdx.x - ATT_BLOCKS;
        int c = cb & (CCH - 1), bh = cb >> 6;
        int b = bh >> 3, h = bh & 7;
        int rg = tid >> 4, f4 = tid & 15;
        const int RS = H * D / 4;

        const float4* vb = (const float4*)(V + ((size_t)(b * L + c * CLEN + rg * 2) * H + h) * D) + f4;
        float4 v0 = vb[0], v1 = vb[RS];
        sp[rg][f4] = f4add(v0, v1);

        float4 gacc = make_float4(0.f, 0.f, 0.f, 0.f);
        const float4* cs4 = (const float4*)g_cs + (size_t)bh * CCH * 16 + f4;
        for (int cc = rg; cc < c; cc += 16) gacc = f4add(gacc, cs4[cc * 16]);
        sg[rg][f4] = gacc;
        __syncthreads();

        float4 run = make_float4(0.f, 0.f, 0.f, 0.f);
        #pragma unroll
        for (int i = 0; i < 16; i++) {
            run = f4add(run, sg[i][f4]);
            if (i < rg) run = f4add(run, sp[i][f4]);
        }

        float4 o0 = f4add(run, v0);
        float4 o1 = f4add(o0, v1);

        float4* ob = (float4*)(out + ((size_t)bh * L + c * CLEN + rg * 2) * D) + f4;
        ob[0] = o0; ob[16] = o1;
    }
}

// ---------------------------------------------------------------------------
// K4: combine valid ks partials, normalize, scatter. grid (10, BH), 256 thr;
// block handles 4 u's (better issue/occupancy than 64-thread blocks).
// ---------------------------------------------------------------------------
__global__ void __launch_bounds__(256)
attn_combine_kernel(float* __restrict__ out) {
    int bh = blockIdx.y;
    int tid = threadIdx.x;
    int u = blockIdx.x * 4 + (tid >> 6);
    int d = tid & 63;

    int uc = u / UPC;
    int lu_hi = g_top[bh * NTOP + uc * UPC + (UPC - 1)];
    int nks = (lu_hi >> 8) + 1;

    size_t base = (size_t)(bh * NTOP + u) * KS;
    float acc = 0.f, lt = 0.f;
    for (int p = 0; p < nks; p++) {
        acc += g_pacc[(base + p) * D + d];
        lt  += g_pl[base + p];
    }
    int lu = g_top[bh * NTOP + u];
    out[((size_t)bh * L + lu) * D + d] = acc / lt;
}

// ---------------------------------------------------------------------------
extern "C" void kernel_launch(void* const* d_in, const int* in_sizes, int n_in,
                              void* d_out, int out_size) {
    const float* Q   = (const float*)d_in[0];
    const float* K   = (const float*)d_in[1];
    const float* V   = (const float*)d_in[2];
    const int*   idx = (const int*)d_in[3];
    float*       out = (float*)d_out;

    mscore_kernel<<<BH * 4, 512>>>(Q, K, idx);
    k2_topk_cumsumA<<<BH + CCH * BH / 2, 256>>>(V);
    k3_attn_cumsumC<<<ATT_BLOCKS + CC_BLOCKS, 256>>>(Q, K, V, out);
    attn_combine_kernel<<<dim3(10, BH), 256>>>(out);
}